// round 4
// baseline (speedup 1.0000x reference)
#include <cuda_runtime.h>
#include <cstddef>

#define LAYERS 5
#define H 128
#define BATCH 256
#define T 2048
#define BBLK 8
#define NBLOCKS (BATCH / BBLK)   // 32
#define NTHREADS 512
#define KSLICES 8
#define KPER 16

typedef unsigned long long ull;

__device__ __forceinline__ ull pack2(float lo, float hi) {
    ull r; asm("mov.b64 %0,{%1,%2};" : "=l"(r) : "f"(lo), "f"(hi)); return r;
}
__device__ __forceinline__ void fma2(ull& acc, ull a, ull b) {
    asm("fma.rn.f32x2 %0,%1,%2,%0;" : "+l"(acc) : "l"(a), "l"(b));
}
__device__ __forceinline__ float fast_sigmoid(float x) {
    return 1.0f / (1.0f + __expf(-x));
}

struct Smem {
    float h_state[LAYERS][BBLK][H];       // 20 KB
    float xcur[2][BBLK][H];               // 8 KB
    float partA[KSLICES][3][BBLK][H];     // 96 KB
    float partB[KSLICES][BBLK][H];        // 32 KB
    float rh[BBLK][H];                    // 4 KB
    float zbuf[BBLK][H];                  // 4 KB
    float preh[BBLK][H];                  // 4 KB
    float bias_r[LAYERS][H];              // 2.5 KB
    float bias_z[LAYERS][H];
    float bias_h[LAYERS][H];
};

__global__ __launch_bounds__(NTHREADS, 1)
void gru_persistent_kernel(
    const float* __restrict__ inp,
    const float* __restrict__ W_hr, const float* __restrict__ W_xr, const float* __restrict__ b_r,
    const float* __restrict__ W_hz, const float* __restrict__ W_xz, const float* __restrict__ b_z,
    const float* __restrict__ W_hh, const float* __restrict__ W_xh, const float* __restrict__ b_h,
    float* __restrict__ out)
{
    extern __shared__ char smem_raw[];
    Smem& sm = *reinterpret_cast<Smem*>(smem_raw);

    const int tid  = threadIdx.x;
    const int jp   = tid & 63;          // column pair index
    const int j0   = jp << 1;           // owns columns j0, j0+1
    const int ks   = tid >> 6;          // k-slice 0..7
    const int k0   = ks * KPER;
    const int row0 = blockIdx.x * BBLK;

    // ---- init ----
    for (int i = tid; i < LAYERS * BBLK * H; i += NTHREADS)
        (&sm.h_state[0][0][0])[i] = 0.0f;
    for (int i = tid; i < LAYERS * H; i += NTHREADS) {
        (&sm.bias_r[0][0])[i] = b_r[i];
        (&sm.bias_z[0][0])[i] = b_z[i];
        (&sm.bias_h[0][0])[i] = b_h[i];
    }
    // preload x_0 : 8 rows x 128 cols = 1024 elements, 2 per thread
    {
        const int pb = tid >> 7;        // 0..3
        const int pk = tid & 127;
        sm.xcur[0][pb][pk]     = inp[((size_t)(row0 + pb) * T) * H + pk];
        sm.xcur[0][pb + 4][pk] = inp[((size_t)(row0 + pb + 4) * T) * H + pk];
    }
    __syncthreads();

    for (int t = 0; t < T; ++t) {
        const int cur = t & 1, nxt = cur ^ 1;

        // prefetch x_{t+1} into registers
        float p0 = 0.f, p1 = 0.f;
        const bool havepre = (t + 1 < T);
        const int pb = tid >> 7, pk = tid & 127;
        if (havepre) {
            p0 = inp[((size_t)(row0 + pb) * T + (t + 1)) * H + pk];
            p1 = inp[((size_t)(row0 + pb + 4) * T + (t + 1)) * H + pk];
        }

        const float(*xin)[H] = sm.xcur[cur];

        #pragma unroll
        for (int l = 0; l < LAYERS; ++l) {
            const float(*hp)[H] = sm.h_state[l];
            const float* whr = W_hr + l * H * H;
            const float* wxr = W_xr + l * H * H;
            const float* whz = W_hz + l * H * H;
            const float* wxz = W_xz + l * H * H;
            const float* wxh = W_xh + l * H * H;
            const float* whh = W_hh + l * H * H;

            // ======== Stage A ========
            ull ar[BBLK], az[BBLK], ax[BBLK];
            #pragma unroll
            for (int b = 0; b < BBLK; ++b) { ar[b] = 0ull; az[b] = 0ull; ax[b] = 0ull; }

            #pragma unroll 4
            for (int kk = 0; kk < KPER; ++kk) {
                const int k = k0 + kk;
                // weights: one LDG.64 = ready-to-use f32x2 operand {j0, j0+1}
                const ull w1 = __ldg(reinterpret_cast<const ull*>(whr + k * H + j0));
                const ull w2 = __ldg(reinterpret_cast<const ull*>(wxr + k * H + j0));
                const ull w3 = __ldg(reinterpret_cast<const ull*>(whz + k * H + j0));
                const ull w4 = __ldg(reinterpret_cast<const ull*>(wxz + k * H + j0));
                const ull w5 = __ldg(reinterpret_cast<const ull*>(wxh + k * H + j0));
                #pragma unroll
                for (int b = 0; b < BBLK; ++b) {
                    const float hv = hp[b][k];        // LDS broadcast
                    const float xv = xin[b][k];
                    const ull h2 = pack2(hv, hv);
                    const ull x2 = pack2(xv, xv);
                    fma2(ar[b], w1, h2);
                    fma2(ar[b], w2, x2);
                    fma2(az[b], w3, h2);
                    fma2(az[b], w4, x2);
                    fma2(ax[b], w5, x2);
                }
            }
            #pragma unroll
            for (int b = 0; b < BBLK; ++b) {
                *reinterpret_cast<ull*>(&sm.partA[ks][0][b][j0]) = ar[b];
                *reinterpret_cast<ull*>(&sm.partA[ks][1][b][j0]) = az[b];
                *reinterpret_cast<ull*>(&sm.partA[ks][2][b][j0]) = ax[b];
            }
            __syncthreads();

            // ---- Combine A : 3*8*128 = 3072 values, 6 per thread ----
            #pragma unroll
            for (int u = 0; u < 6; ++u) {
                const int i = tid + u * NTHREADS;
                const int g = i >> 10;
                const int r = i & 1023;
                const int b = r >> 7;
                const int j = r & 127;
                float ssum = 0.f;
                #pragma unroll
                for (int ss = 0; ss < KSLICES; ++ss) ssum += sm.partA[ss][g][b][j];
                if (g == 0) {
                    const float R = fast_sigmoid(ssum + sm.bias_r[l][j]);
                    sm.rh[b][j] = R * sm.h_state[l][b][j];
                } else if (g == 1) {
                    sm.zbuf[b][j] = fast_sigmoid(ssum + sm.bias_z[l][j]);
                } else {
                    sm.preh[b][j] = ssum + sm.bias_h[l][j];
                }
            }
            __syncthreads();

            // ======== Stage B: (R*h) @ W_hh ========
            ull bh[BBLK];
            #pragma unroll
            for (int b = 0; b < BBLK; ++b) bh[b] = 0ull;

            #pragma unroll 4
            for (int kk = 0; kk < KPER; ++kk) {
                const int k = k0 + kk;
                const ull w = __ldg(reinterpret_cast<const ull*>(whh + k * H + j0));
                #pragma unroll
                for (int b = 0; b < BBLK; ++b) {
                    const float rv = sm.rh[b][k];
                    fma2(bh[b], w, pack2(rv, rv));
                }
            }
            #pragma unroll
            for (int b = 0; b < BBLK; ++b)
                *reinterpret_cast<ull*>(&sm.partB[ks][b][j0]) = bh[b];
            __syncthreads();

            // ---- Combine B : 8*128 = 1024 values, 2 per thread ----
            #pragma unroll
            for (int u = 0; u < 2; ++u) {
                const int i = tid + u * NTHREADS;
                const int b = i >> 7;
                const int j = i & 127;
                float ssum = 0.f;
                #pragma unroll
                for (int ss = 0; ss < KSLICES; ++ss) ssum += sm.partB[ss][b][j];
                const float hpre = ssum + sm.preh[b][j];
                const float htld = tanhf(hpre);
                const float Z    = sm.zbuf[b][j];
                const float hn   = Z * htld + (1.0f - Z) * sm.h_state[l][b][j];
                sm.h_state[l][b][j] = hn;
                if (l == LAYERS - 1)
                    out[((size_t)(row0 + b) * T + t) * H + j] = hn;
            }
            __syncthreads();

            xin = sm.h_state[l];
        }

        // stash prefetched x_{t+1}
        if (havepre) {
            sm.xcur[nxt][pb][pk]     = p0;
            sm.xcur[nxt][pb + 4][pk] = p1;
        }
        __syncthreads();
    }
}

extern "C" void kernel_launch(void* const* d_in, const int* in_sizes, int n_in,
                              void* d_out, int out_size) {
    (void)in_sizes; (void)n_in; (void)out_size;
    const float* inp  = (const float*)d_in[0];
    const float* W_hr = (const float*)d_in[1];
    const float* W_xr = (const float*)d_in[2];
    const float* b_r  = (const float*)d_in[3];
    const float* W_hz = (const float*)d_in[4];
    const float* W_xz = (const float*)d_in[5];
    const float* b_z  = (const float*)d_in[6];
    const float* W_hh = (const float*)d_in[7];
    const float* W_xh = (const float*)d_in[8];
    const float* b_h  = (const float*)d_in[9];
    float* out = (float*)d_out;

    cudaFuncSetAttribute(gru_persistent_kernel,
                         cudaFuncAttributeMaxDynamicSharedMemorySize,
                         (int)sizeof(Smem));
    gru_persistent_kernel<<<NBLOCKS, NTHREADS, sizeof(Smem)>>>(
        inp, W_hr, W_xr, b_r, W_hz, W_xz, b_z, W_hh, W_xh, b_h, out);
}

// round 5
// speedup vs baseline: 3.1445x; 3.1445x over previous
#include <cuda_runtime.h>
#include <cstddef>
#include <cstdint>

#define LAYERS 5
#define H 128
#define T 2048
#define BATCH 256
#define G 29           // batch groups per layer
#define BG 9           // rows per group (29*9 = 261 >= 256)
#define BPAD 264       // padded batch rows in staging buffer
#define NTH 512
#define KS 8           // k-slices
#define KPER 16        // k rows per slice
#define CHUNK 8        // flag publish granularity (power of 2)

typedef unsigned long long ull;

// Inter-layer staging: Xbuf[l][t][row][j] holds output of layer l (l=0..3)
__device__ float Xbuf[(size_t)(LAYERS - 1) * T * BPAD * H];   // ~1.03 GB
__device__ int progressFlag[LAYERS * G];

__device__ __forceinline__ ull pack2(float lo, float hi) {
    ull r; asm("mov.b64 %0,{%1,%2};" : "=l"(r) : "f"(lo), "f"(hi)); return r;
}
__device__ __forceinline__ void fma2(ull& acc, ull a, ull b) {
    asm("fma.rn.f32x2 %0,%1,%2,%0;" : "+l"(acc) : "l"(a), "l"(b));
}
__device__ __forceinline__ float lo_of(ull v) {
    return __uint_as_float((unsigned)(v & 0xffffffffull));
}
__device__ __forceinline__ float fast_sigmoid(float x) {
    return 1.0f / (1.0f + __expf(-x));
}
__device__ __forceinline__ int ld_acquire(const int* p) {
    int v; asm volatile("ld.acquire.gpu.s32 %0,[%1];" : "=r"(v) : "l"(p) : "memory"); return v;
}
__device__ __forceinline__ void st_release(int* p, int v) {
    asm volatile("st.release.gpu.s32 [%0],%1;" :: "l"(p), "r"(v) : "memory");
}

struct Smem {
    float partA[KS][3][BG][H];   // 110592 B
    float partB[KS][BG][H];      //  36864 B
    ull   h2[BG][H];             //   9216 B  (h replicated as f32x2)
    ull   x2[BG][H];             //   9216 B
    ull   rh2[BG][H];            //   9216 B  (R*h replicated)
    float zbuf[BG][H];           //   4608 B
    float preh[BG][H];           //   4608 B
    float br[H];                 //    512 B
    float bz[H];
    float bh_[H];
    int   avail_sh;
};                               // ~186 KB

__global__ void reset_kernel() {
    int i = threadIdx.x;
    if (i < LAYERS * G) progressFlag[i] = 0;
}

__global__ __launch_bounds__(NTH, 1)
void gru_layer_kernel(
    const float* __restrict__ inp,
    const float* __restrict__ W_hr, const float* __restrict__ W_xr, const float* __restrict__ b_r,
    const float* __restrict__ W_hz, const float* __restrict__ W_xz, const float* __restrict__ b_z,
    const float* __restrict__ W_hh, const float* __restrict__ W_xh, const float* __restrict__ b_h,
    float* __restrict__ out)
{
    extern __shared__ char smem_raw[];
    Smem& sm = *reinterpret_cast<Smem*>(smem_raw);

    const int bid  = blockIdx.x;
    const int l    = bid / G;          // my layer
    const int g    = bid % G;          // my batch group
    const int row0 = g * BG;
    const int tid  = threadIdx.x;
    const int jp   = tid & 63;         // column pair
    const int j0   = jp << 1;
    const int ks   = tid >> 6;         // k-slice 0..7
    const int k0   = ks * KPER;

    const float* whr = W_hr + l * H * H;
    const float* wxr = W_xr + l * H * H;
    const float* whz = W_hz + l * H * H;
    const float* wxz = W_xz + l * H * H;
    const float* wxh = W_xh + l * H * H;
    const float* whh = W_hh + l * H * H;

    // init: h=0, biases to smem
    for (int i = tid; i < BG * H; i += NTH)
        (&sm.h2[0][0])[i] = 0ull;
    for (int i = tid; i < H; i += NTH) {
        sm.br[i]  = b_r[l * H + i];
        sm.bz[i]  = b_z[l * H + i];
        sm.bh_[i] = b_h[l * H + i];
    }
    __syncthreads();

    int avail = (l == 0) ? T : 0;
    const float* xsrc = (l == 0) ? nullptr : &Xbuf[(size_t)(l - 1) * T * BPAD * H];
    float* ysnk = (l == LAYERS - 1) ? nullptr : &Xbuf[(size_t)l * T * BPAD * H];
    int* myflag  = &progressFlag[l * G + g];
    int* srcflag = (l == 0) ? nullptr : &progressFlag[(l - 1) * G + g];

    for (int t = 0; t < T; ++t) {
        // ---- wait for producer (chunked) ----
        if (t >= avail) {
            if (tid == 0) {
                const int need = t + 1;
                int v = ld_acquire(srcflag);
                while (v < need) { __nanosleep(200); v = ld_acquire(srcflag); }
                sm.avail_sh = v;
            }
            __syncthreads();
            avail = sm.avail_sh;
        }

        // ---- load x_t into smem as replicated f32x2 ----
        for (int i = tid; i < BG * H; i += NTH) {
            const int b = i >> 7, k = i & 127;
            const int row = row0 + b;
            float v;
            if (l == 0) {
                v = (row < BATCH) ? inp[((size_t)row * T + t) * H + k] : 0.0f;
            } else {
                v = xsrc[((size_t)t * BPAD + row) * H + k];
            }
            sm.x2[b][k] = pack2(v, v);
        }
        __syncthreads();

        // ======== Stage A: r, z, xh preact partials over my k-slice ========
        {
            ull ar[BG], az[BG], ax[BG];
            #pragma unroll
            for (int b = 0; b < BG; ++b) { ar[b] = 0ull; az[b] = 0ull; ax[b] = 0ull; }

            #pragma unroll 2
            for (int kk = 0; kk < KPER; ++kk) {
                const int k = k0 + kk;
                const ull w1 = __ldg(reinterpret_cast<const ull*>(whr + k * H + j0));
                const ull w2 = __ldg(reinterpret_cast<const ull*>(wxr + k * H + j0));
                const ull w3 = __ldg(reinterpret_cast<const ull*>(whz + k * H + j0));
                const ull w4 = __ldg(reinterpret_cast<const ull*>(wxz + k * H + j0));
                const ull w5 = __ldg(reinterpret_cast<const ull*>(wxh + k * H + j0));
                #pragma unroll
                for (int b = 0; b < BG; ++b) {
                    const ull hb = sm.h2[b][k];   // LDS.64 broadcast
                    const ull xb = sm.x2[b][k];
                    fma2(ar[b], w1, hb);
                    fma2(ar[b], w2, xb);
                    fma2(az[b], w3, hb);
                    fma2(az[b], w4, xb);
                    fma2(ax[b], w5, xb);
                }
            }
            #pragma unroll
            for (int b = 0; b < BG; ++b) {
                *reinterpret_cast<ull*>(&sm.partA[ks][0][b][j0]) = ar[b];
                *reinterpret_cast<ull*>(&sm.partA[ks][1][b][j0]) = az[b];
                *reinterpret_cast<ull*>(&sm.partA[ks][2][b][j0]) = ax[b];
            }
        }
        __syncthreads();

        // ---- Combine A: reduce slices, activations ----
        for (int i = tid; i < 3 * BG * H; i += NTH) {
            const int g3 = i / (BG * H);
            const int r  = i % (BG * H);
            const int b  = r >> 7;
            const int j  = r & 127;
            float ssum = 0.f;
            #pragma unroll
            for (int ss = 0; ss < KS; ++ss) ssum += sm.partA[ss][g3][b][j];
            if (g3 == 0) {
                const float R  = fast_sigmoid(ssum + sm.br[j]);
                const float rv = R * lo_of(sm.h2[b][j]);
                sm.rh2[b][j] = pack2(rv, rv);
            } else if (g3 == 1) {
                sm.zbuf[b][j] = fast_sigmoid(ssum + sm.bz[j]);
            } else {
                sm.preh[b][j] = ssum + sm.bh_[j];
            }
        }
        __syncthreads();

        // ======== Stage B: (R*h) @ W_hh partials ========
        {
            ull bh[BG];
            #pragma unroll
            for (int b = 0; b < BG; ++b) bh[b] = 0ull;

            #pragma unroll 2
            for (int kk = 0; kk < KPER; ++kk) {
                const int k = k0 + kk;
                const ull w = __ldg(reinterpret_cast<const ull*>(whh + k * H + j0));
                #pragma unroll
                for (int b = 0; b < BG; ++b)
                    fma2(bh[b], w, sm.rh2[b][k]);
            }
            #pragma unroll
            for (int b = 0; b < BG; ++b)
                *reinterpret_cast<ull*>(&sm.partB[ks][b][j0]) = bh[b];
        }
        __syncthreads();

        // ---- Combine B: tanh + blend, update h, emit ----
        for (int i = tid; i < BG * H; i += NTH) {
            const int b = i >> 7;
            const int j = i & 127;
            float ssum = 0.f;
            #pragma unroll
            for (int ss = 0; ss < KS; ++ss) ssum += sm.partB[ss][b][j];
            const float htld = tanhf(ssum + sm.preh[b][j]);
            const float Z    = sm.zbuf[b][j];
            const float hv   = lo_of(sm.h2[b][j]);
            const float hn   = Z * htld + (1.0f - Z) * hv;
            sm.h2[b][j] = pack2(hn, hn);
            const int row = row0 + b;
            if (l == LAYERS - 1) {
                if (row < BATCH)
                    out[((size_t)row * T + t) * H + j] = hn;
            } else {
                ysnk[((size_t)t * BPAD + row) * H + j] = hn;
            }
        }
        __syncthreads();

        // ---- publish progress (chunked) ----
        if (l < LAYERS - 1 && tid == 0) {
            const int t1 = t + 1;
            if ((t1 & (CHUNK - 1)) == 0 || t1 == T) {
                __threadfence();
                st_release(myflag, t1);
            }
        }
    }
}

extern "C" void kernel_launch(void* const* d_in, const int* in_sizes, int n_in,
                              void* d_out, int out_size) {
    (void)in_sizes; (void)n_in; (void)out_size;
    const float* inp  = (const float*)d_in[0];
    const float* W_hr = (const float*)d_in[1];
    const float* W_xr = (const float*)d_in[2];
    const float* b_r  = (const float*)d_in[3];
    const float* W_hz = (const float*)d_in[4];
    const float* W_xz = (const float*)d_in[5];
    const float* b_z  = (const float*)d_in[6];
    const float* W_hh = (const float*)d_in[7];
    const float* W_xh = (const float*)d_in[8];
    const float* b_h  = (const float*)d_in[9];
    float* out = (float*)d_out;

    reset_kernel<<<1, 256>>>();

    cudaFuncSetAttribute(gru_layer_kernel,
                         cudaFuncAttributeMaxDynamicSharedMemorySize,
                         (int)sizeof(Smem));
    gru_layer_kernel<<<LAYERS * G, NTH, sizeof(Smem)>>>(
        inp, W_hr, W_xr, b_r, W_hz, W_xz, b_z, W_hh, W_xh, b_h, out);
}